// round 4
// baseline (speedup 1.0000x reference)
#include <cuda_runtime.h>
#include <stdint.h>

#define EMB 64
#define HIST 50
#define ROW_F4 (HIST * EMB / 4)   // 800 float4 per output row
#define ENT_F4 (EMB / 4)          // 16 float4 per embedding entry
#define ROWS_PER_BLK 8
#define MAX_BATCH (1 << 21)

// row_start[b] = first index i with pos[i] >= b ; row_start[batch] = n_valid
__device__ int g_row_start[MAX_BATCH + 1];

__global__ void __launch_bounds__(256) boundaries_kernel(
    const int* __restrict__ pos, int n_valid, int batch)
{
    int i = blockIdx.x * blockDim.x + threadIdx.x;
    if (i > n_valid) return;
    int cur  = (i < n_valid) ? pos[i]     : batch;
    int prev = (i > 0)       ? pos[i - 1] : -1;
    for (int b = prev + 1; b <= cur; b++) {
        if (b <= batch) g_row_start[b] = i;
    }
    if (i == 0) g_row_start[0] = 0;
}

// 8 rows per block; boundaries staged in smem; 4 independent ld/st chains
// per thread per row for MLP.
__global__ void __launch_bounds__(256) remap_kernel(
    const float4* __restrict__ emb,
    float4* __restrict__ out,
    int batch)
{
    __shared__ int s_start[ROWS_PER_BLK + 1];

    const int b0 = blockIdx.x * ROWS_PER_BLK;
    int nrows = batch - b0;
    if (nrows > ROWS_PER_BLK) nrows = ROWS_PER_BLK;

    const int tid = threadIdx.x;
    if (tid <= nrows) s_start[tid] = g_row_start[b0 + tid];
    __syncthreads();

    const float4 zero = make_float4(0.f, 0.f, 0.f, 0.f);

    for (int r = 0; r < nrows; r++) {
        const int start = s_start[r];
        int cnt_f4 = (s_start[r + 1] - start) * ENT_F4;
        if (cnt_f4 > ROW_F4) cnt_f4 = ROW_F4;   // mode="drop" clamp

        float4* __restrict__ orow = out + (size_t)(b0 + r) * ROW_F4;
        const float4* __restrict__ irow = emb + (size_t)start * ENT_F4;

        const int v0 = tid;
        const int v1 = tid + 256;
        const int v2 = tid + 512;
        const int v3 = tid + 768;          // only valid for tid < 32

        // front-batch 4 independent loads (MLP=4), then 4 stores
        float4 a0 = (v0 < cnt_f4) ? __ldcs(&irow[v0]) : zero;
        float4 a1 = (v1 < cnt_f4) ? __ldcs(&irow[v1]) : zero;
        float4 a2 = (v2 < cnt_f4) ? __ldcs(&irow[v2]) : zero;
        float4 a3 = (v3 < ROW_F4 && v3 < cnt_f4) ? __ldcs(&irow[v3]) : zero;

        __stcs(&orow[v0], a0);
        __stcs(&orow[v1], a1);
        __stcs(&orow[v2], a2);
        if (v3 < ROW_F4) __stcs(&orow[v3], a3);
    }
}

extern "C" void kernel_launch(void* const* d_in, const int* in_sizes, int n_in,
                              void* d_out, int out_size)
{
    const float4* emb = (const float4*)d_in[0];
    const int*    pos = (const int*)d_in[1];
    const int n_valid = in_sizes[1];
    const int batch   = out_size / (HIST * EMB);

    int bthreads = n_valid + 1;
    boundaries_kernel<<<(bthreads + 255) / 256, 256>>>(pos, n_valid, batch);

    int cblocks = (batch + ROWS_PER_BLK - 1) / ROWS_PER_BLK;
    remap_kernel<<<cblocks, 256>>>(emb, (float4*)d_out, batch);
}